// round 3
// baseline (speedup 1.0000x reference)
#include <cuda_runtime.h>

// Problem shape (fixed by the dataset)
#define Lc 128
#define Sc 2048
#define Bc 128
#define IGNORE_IDX (-100)

// Scratch (no cudaMalloc allowed)
__device__ float g_E[Lc * Lc];
__device__ float g_logz[Bc];
__device__ float g_score[Bc];

// ---------------------------------------------------------------------------
// Kernel 1: E = exp(T), computed once per launch (cheap, deterministic)
// ---------------------------------------------------------------------------
__global__ void prep_E(const float* __restrict__ trans) {
    int i = blockIdx.x * blockDim.x + threadIdx.x;
    if (i < Lc * Lc) g_E[i] = expf(trans[i]);
}

// ---------------------------------------------------------------------------
// Kernel 2: per-batch CRF forward scan + gold score.
// One CTA per batch, one thread per state column j.
// E-column cached in registers; p double-buffered in smem.
// ---------------------------------------------------------------------------
__global__ __launch_bounds__(Lc, 1) void crf_kernel(
    const float* __restrict__ em,     // [B,S,L] f32
    const int* __restrict__ mask,     // [B,S] int32 (bool promoted by harness)
    const int* __restrict__ tags,     // [B,S] int32 (int64 demoted by harness)
    const float* __restrict__ trans,  // [L,L] f32
    const float* __restrict__ startt, // [L]
    const float* __restrict__ endt)   // [L]
{
    const int b = blockIdx.x;
    const int j = threadIdx.x;
    const int lane = j & 31;
    const int wid  = j >> 5;

    __shared__ float pbuf[2][Lc];
    __shared__ float redf[4];
    __shared__ int   redi[4];

    const int*   tg  = tags + (long long)b * Sc;
    const float* emb = em   + (long long)b * Sc * Lc;
    const int*   mk  = mask + (long long)b * Sc;

    // ---------------- gold-path score ----------------
    float sc = 0.f;
    int lastIdx = -1;
    for (int t = j; t < Sc; t += Lc) {
        int tt = tg[t];
        bool v = (tt != IGNORE_IDX);
        int st = v ? tt : 0;
        if (v && t > lastIdx) lastIdx = t;
        if (t == 0) {
            if (v) sc += startt[st];
        } else if (v) {
            int tp = tg[t - 1];
            int sp = (tp != IGNORE_IDX) ? tp : 0;
            sc += trans[sp * Lc + st] + emb[(long long)t * Lc + st];
        }
    }
#pragma unroll
    for (int o = 16; o > 0; o >>= 1) {
        sc += __shfl_xor_sync(0xffffffffu, sc, o);
        lastIdx = max(lastIdx, __shfl_xor_sync(0xffffffffu, lastIdx, o));
    }
    if (lane == 0) { redf[wid] = sc; redi[wid] = lastIdx; }
    __syncthreads();
    if (j == 0) {
        float s = redf[0] + redf[1] + redf[2] + redf[3];
        int li = max(max(redi[0], redi[1]), max(redi[2], redi[3]));
        if (li >= 0) {
            int lt = tg[li];
            int slt = (lt != IGNORE_IDX) ? lt : 0;
            s += endt[slt];
        }
        g_score[b] = s;
    }

    // ---------------- load E column into registers ----------------
    float Ecol[Lc];
#pragma unroll
    for (int i = 0; i < Lc; i++) Ecol[i] = g_E[i * Lc + j];

    // ---------------- forward scan (prob domain) ----------------
    // Invariant: alpha[j] = C + log(pbuf[cur][j])
    pbuf[0][j] = __expf(startt[j] + emb[j]);
    float C = 0.f;
    int cur = 0;
    __syncthreads();

    float em_next = emb[Lc + j];          // emissions for t=1
    int   m_next  = mk[1];
    for (int t = 1; t < Sc; ++t) {
        float em_cur = em_next;
        int m = m_next;
        if (t + 1 < Sc) {                 // prefetch next step
            em_next = emb[(long long)(t + 1) * Lc + j];
            m_next  = mk[t + 1];
        }
        if (m) {                          // uniform across the CTA
            const float4* p4 = (const float4*)pbuf[cur];
            float q0 = 0.f, q1 = 0.f, q2 = 0.f, q3 = 0.f;
#pragma unroll
            for (int k = 0; k < Lc / 4; k++) {
                float4 pv = p4[k];        // broadcast LDS.128
                q0 = fmaf(pv.x, Ecol[4 * k + 0], q0);
                q1 = fmaf(pv.y, Ecol[4 * k + 1], q1);
                q2 = fmaf(pv.z, Ecol[4 * k + 2], q2);
                q3 = fmaf(pv.w, Ecol[4 * k + 3], q3);
            }
            float r = pbuf[cur][0];       // renorm constant = state-0 value
            float inv = __fdividef(1.0f, r);
            float q = ((q0 + q1) + (q2 + q3)) * inv * __expf(em_cur);
            C += __logf(r);
            pbuf[cur ^ 1][j] = q;
            __syncthreads();
            cur ^= 1;
        }
        // masked step: alpha (and C) unchanged, nothing to do
    }

    // ---------------- finalize log_z ----------------
    float v = pbuf[cur][j] * __expf(endt[j]);
#pragma unroll
    for (int o = 16; o > 0; o >>= 1) v += __shfl_xor_sync(0xffffffffu, v, o);
    if (lane == 0) redf[wid] = v;
    __syncthreads();
    if (j == 0) {
        float s = redf[0] + redf[1] + redf[2] + redf[3];
        g_logz[b] = C + logf(s);
    }
}

// ---------------------------------------------------------------------------
// Kernel 3: out = mean(log_z - score)
// ---------------------------------------------------------------------------
__global__ void final_reduce(float* __restrict__ out) {
    int j = threadIdx.x;
    float v = g_logz[j] - g_score[j];
#pragma unroll
    for (int o = 16; o > 0; o >>= 1) v += __shfl_xor_sync(0xffffffffu, v, o);
    __shared__ float red[4];
    if ((j & 31) == 0) red[j >> 5] = v;
    __syncthreads();
    if (j == 0) out[0] = (red[0] + red[1] + red[2] + red[3]) * (1.0f / (float)Bc);
}

// ---------------------------------------------------------------------------
extern "C" void kernel_launch(void* const* d_in, const int* in_sizes, int n_in,
                              void* d_out, int out_size) {
    const float* em     = (const float*)d_in[0];
    const int*   mask   = (const int*)d_in[1];
    const int*   tags   = (const int*)d_in[2];
    const float* trans  = (const float*)d_in[3];
    const float* startt = (const float*)d_in[4];
    const float* endt   = (const float*)d_in[5];
    (void)in_sizes; (void)n_in; (void)out_size;

    prep_E<<<(Lc * Lc + 255) / 256, 256>>>(trans);
    crf_kernel<<<Bc, Lc>>>(em, mask, tags, trans, startt, endt);
    final_reduce<<<1, 128>>>((float*)d_out);
}